// round 15
// baseline (speedup 1.0000x reference)
#include <cuda_runtime.h>
#include <cuda_fp16.h>
#include <math.h>

#define NN 50000
#define EE 800000
#define DD 256
#define HH 8
#define ND (NN * DD)
#define EH (EE * HH)
#define NC0 25088   // agg/gemm2 chunk split (multiple of 128)
#define LAMBDA_INIT 0.6321205588285577f

// ---------------- scratch (static device globals; no allocation) ----------------
__device__ __half g_Vh[ND];        // V = x @ v_w^T (fp16)   25.6 MB
__device__ float  g_exp[EE * 16];  // exp(scores), edge order 51.2 MB
__device__ __half g_acch[ND];      // aggregated output fp16 25.6 MB
__device__ int    g_cnt[NN];       // per-node degree
__device__ int    g_off[NN];       // CSR offsets
__device__ int    g_cur[NN];       // fill cursors
__device__ int    g_eid[EE];       // sorted edge ids
__device__ int    g_esrc[EE];      // sorted src nodes
__device__ float  g_beta;
__device__ int    g_is64;

// ---------------- helpers ----------------
__device__ __forceinline__ int ldidx(const void* p, long long i, int is64) {
    return is64 ? (int)((const long long*)p)[i] : ((const int*)p)[i];
}
__device__ __forceinline__ unsigned f2tf32(float x) {
    unsigned r;
    asm("cvt.rna.tf32.f32 %0, %1;" : "=r"(r) : "f"(x));
    return r;
}
__device__ __forceinline__ void mma_tf32(float4& c,
                                         unsigned a0, unsigned a1, unsigned a2, unsigned a3,
                                         unsigned b0, unsigned b1) {
    asm volatile("mma.sync.aligned.m16n8k8.row.col.f32.tf32.tf32.f32 "
                 "{%0,%1,%2,%3}, {%4,%5,%6,%7}, {%8,%9}, {%0,%1,%2,%3};"
                 : "+f"(c.x), "+f"(c.y), "+f"(c.z), "+f"(c.w)
                 : "r"(a0), "r"(a1), "r"(a2), "r"(a3), "r"(b0), "r"(b1));
}
__device__ __forceinline__ void mma_f16(float4& c,
                                        unsigned a0, unsigned a1, unsigned a2, unsigned a3,
                                        unsigned b0, unsigned b1) {
    asm volatile("mma.sync.aligned.m16n8k16.row.col.f32.f16.f16.f32 "
                 "{%0,%1,%2,%3}, {%4,%5,%6,%7}, {%8,%9}, {%0,%1,%2,%3};"
                 : "+f"(c.x), "+f"(c.y), "+f"(c.z), "+f"(c.w)
                 : "r"(a0), "r"(a1), "r"(a2), "r"(a3), "r"(b0), "r"(b1));
}

// exact-enough GELU: s * Phi(s), Phi via Abramowitz-Stegun 7.1.26 erf (abs err 1.5e-7)
__device__ __forceinline__ float gelu_f(float s) {
    float x  = s * 0.70710678118654752f;
    float ax = fabsf(x);
    float t  = __fdividef(1.0f, fmaf(0.3275911f, ax, 1.0f));
    float p  = fmaf(1.061405429f, t, -1.453152027f);
    p = fmaf(p, t, 1.421413741f);
    p = fmaf(p, t, -0.284496736f);
    p = fmaf(p, t, 0.254829592f);
    p *= t;
    float e = __expf(-x * x);
    float erfax = fmaf(-p, e, 1.0f);
    float erfx  = copysignf(erfax, x);
    return s * 0.5f * (1.0f + erfx);
}

// ---------------- fused prologue: zero counters + dtype sniff + beta ----------------
__global__ void k_prolog(const void* ei, const float* __restrict__ lq,
                         const float* __restrict__ lk, float* out_beta) {
    int i = blockIdx.x * blockDim.x + threadIdx.x;
    if (i < NN) g_cnt[i] = 0;

    if (blockIdx.x == 0) {
        int t = threadIdx.x;
        const int* p = (const int*)ei;
        int nz = (p[2 * t + 1] != 0);
        int any = __syncthreads_or(nz);
        if (t == 0) g_is64 = !any;
        __shared__ float red[128];
        if (t < 128) {
            float pr = (t < 100) ? lq[t] * lk[t] : 0.0f;
            red[t] = pr;
        }
        __syncthreads();
        for (int s = 64; s > 0; s >>= 1) {
            if (t < s) red[t] += red[t + s];
            __syncthreads();
        }
        if (t == 0) {
            float lam1 = expf(red[0]);
            float b = 1.0f / (1.0f + expf(-lam1 * LAMBDA_INIT));
            g_beta = b;
            if (out_beta) *out_beta = b;
        }
    }
}

// ---------------- CSR build ----------------
__global__ void k_hist(const void* __restrict__ ei) {
    int e = blockIdx.x * blockDim.x + threadIdx.x;
    if (e >= EE) return;
    int tgt = ldidx(ei, (long long)EE + e, g_is64);
    atomicAdd(&g_cnt[tgt], 1);
}

__global__ void k_scan() {
    __shared__ int s[1024];
    __shared__ int carry;
    int tid = threadIdx.x;
    if (tid == 0) carry = 0;
    __syncthreads();
    for (int base = 0; base < NN; base += 1024) {
        int i = base + tid;
        int v = (i < NN) ? g_cnt[i] : 0;
        s[tid] = v;
        __syncthreads();
        #pragma unroll
        for (int d = 1; d < 1024; d <<= 1) {
            int t = (tid >= d) ? s[tid - d] : 0;
            __syncthreads();
            s[tid] += t;
            __syncthreads();
        }
        int excl = s[tid] - v + carry;
        if (i < NN) { g_off[i] = excl; g_cur[i] = excl; }
        __syncthreads();
        if (tid == 0) carry += s[1023];
        __syncthreads();
    }
}

__global__ void k_fill(const void* __restrict__ ei) {
    int e = blockIdx.x * blockDim.x + threadIdx.x;
    if (e >= EE) return;
    int is64 = g_is64;
    int tgt = ldidx(ei, (long long)EE + e, is64);
    int src = ldidx(ei, e, is64);
    int pos = atomicAdd(&g_cur[tgt], 1);
    g_eid[pos] = e;
    g_esrc[pos] = src;
}

// ---------------- tensor-core GEMM1 (3xTF32): Vh[M,256] = A[M,256] @ B[256,256]^T -----
__global__ void __launch_bounds__(256, 2)
k_gemm_tc(const float* __restrict__ A, const float* __restrict__ B,
          __half* __restrict__ Ch, int M) {
    __shared__ float As[128][36];
    __shared__ float Bs[128][36];

    int bm = blockIdx.y * 128, bn = blockIdx.x * 128;
    int tid = threadIdx.x;
    int w = tid >> 5;
    int lane = tid & 31;
    int gid = lane >> 2;
    int tig = lane & 3;
    int wm = (w & 3) * 32;
    int wn = (w >> 2) * 64;

    int lrow = tid >> 1;
    int lcb = (tid & 1) * 16;
    int arow = bm + lrow;
    bool inM = (arow < M);
    const float* Arow = &A[(size_t)(inM ? arow : 0) * DD];
    const float* Brow = &B[(size_t)(bn + lrow) * DD];

    float4 c[2][8];
    #pragma unroll
    for (int i = 0; i < 2; i++)
        #pragma unroll
        for (int j = 0; j < 8; j++)
            c[i][j] = make_float4(0.f, 0.f, 0.f, 0.f);

    #pragma unroll 1
    for (int k0 = 0; k0 < 256; k0 += 32) {
        #pragma unroll
        for (int u = 0; u < 4; u++) {
            float4 av = inM ? *(const float4*)&Arow[k0 + lcb + 4 * u]
                            : make_float4(0.f, 0.f, 0.f, 0.f);
            float4 bv = *(const float4*)&Brow[k0 + lcb + 4 * u];
            *(float4*)&As[lrow][lcb + 4 * u] = av;
            *(float4*)&Bs[lrow][lcb + 4 * u] = bv;
        }
        __syncthreads();

        #pragma unroll
        for (int kk = 0; kk < 32; kk += 8) {
            unsigned ahi[2][4], alo[2][4];
            #pragma unroll
            for (int i = 0; i < 2; i++) {
                int r0 = wm + i * 16 + gid;
                float a0 = As[r0][kk + tig];
                float a1 = As[r0 + 8][kk + tig];
                float a2 = As[r0][kk + tig + 4];
                float a3 = As[r0 + 8][kk + tig + 4];
                ahi[i][0] = f2tf32(a0); alo[i][0] = __float_as_uint(a0 - __uint_as_float(ahi[i][0]));
                ahi[i][1] = f2tf32(a1); alo[i][1] = __float_as_uint(a1 - __uint_as_float(ahi[i][1]));
                ahi[i][2] = f2tf32(a2); alo[i][2] = __float_as_uint(a2 - __uint_as_float(ahi[i][2]));
                ahi[i][3] = f2tf32(a3); alo[i][3] = __float_as_uint(a3 - __uint_as_float(ahi[i][3]));
            }
            #pragma unroll
            for (int j = 0; j < 8; j++) {
                int n0 = wn + j * 8 + gid;
                float b0 = Bs[n0][kk + tig];
                float b1 = Bs[n0][kk + tig + 4];
                unsigned bh0 = f2tf32(b0), bh1 = f2tf32(b1);
                unsigned bl0 = __float_as_uint(b0 - __uint_as_float(bh0));
                unsigned bl1 = __float_as_uint(b1 - __uint_as_float(bh1));
                #pragma unroll
                for (int i = 0; i < 2; i++) {
                    mma_tf32(c[i][j], ahi[i][0], ahi[i][1], ahi[i][2], ahi[i][3], bh0, bh1);
                    mma_tf32(c[i][j], ahi[i][0], ahi[i][1], ahi[i][2], ahi[i][3], bl0, bl1);
                    mma_tf32(c[i][j], alo[i][0], alo[i][1], alo[i][2], alo[i][3], bh0, bh1);
                }
            }
        }
        __syncthreads();
    }

    #pragma unroll
    for (int i = 0; i < 2; i++) {
        int r0 = bm + wm + i * 16 + gid;
        int r1 = r0 + 8;
        #pragma unroll
        for (int j = 0; j < 8; j++) {
            int col = bn + wn + j * 8 + 2 * tig;
            if (r0 < M) {
                __half2 h = __floats2half2_rn(c[i][j].x, c[i][j].y);
                *(__half2*)&Ch[(size_t)r0 * DD + col] = h;
            }
            if (r1 < M) {
                __half2 h = __floats2half2_rn(c[i][j].z, c[i][j].w);
                *(__half2*)&Ch[(size_t)r1 * DD + col] = h;
            }
        }
    }
}

// ---------------- GEMM2 (fp16 HMMA): C[row0+r,256] = Ah[row0+r,256] @ B[256,256]^T ----
__global__ void __launch_bounds__(256, 2)
k_gemm2_h(const __half* __restrict__ A, const float* __restrict__ B,
          float* __restrict__ C, int row0, int rows) {
    __shared__ __half As[128][40];
    __shared__ __half Bs[128][40];

    int bm = blockIdx.y * 128, bn = blockIdx.x * 128;
    int tid = threadIdx.x;
    int w = tid >> 5;
    int lane = tid & 31;
    int gid = lane >> 2;
    int tig = lane & 3;
    int wm = (w & 3) * 32;
    int wn = (w >> 2) * 64;

    int lrow = tid >> 1;
    int lcb = (tid & 1) * 16;
    int arow = bm + lrow;
    bool inM = (arow < rows);
    const __half* Arow = &A[(size_t)(row0 + (inM ? arow : 0)) * DD];
    const float* Brow = &B[(size_t)(bn + lrow) * DD];

    float4 c[2][8];
    #pragma unroll
    for (int i = 0; i < 2; i++)
        #pragma unroll
        for (int j = 0; j < 8; j++)
            c[i][j] = make_float4(0.f, 0.f, 0.f, 0.f);

    #pragma unroll 1
    for (int k0 = 0; k0 < 256; k0 += 32) {
        uint4 zz = make_uint4(0u, 0u, 0u, 0u);
        uint4 av0 = inM ? *(const uint4*)&Arow[k0 + lcb]     : zz;
        uint4 av1 = inM ? *(const uint4*)&Arow[k0 + lcb + 8] : zz;
        *(uint4*)&As[lrow][lcb]     = av0;
        *(uint4*)&As[lrow][lcb + 8] = av1;
        #pragma unroll
        for (int u = 0; u < 4; u++) {
            float4 bv = *(const float4*)&Brow[k0 + lcb + 4 * u];
            __half2 h01 = __floats2half2_rn(bv.x, bv.y);
            __half2 h23 = __floats2half2_rn(bv.z, bv.w);
            *(__half2*)&Bs[lrow][lcb + 4 * u]     = h01;
            *(__half2*)&Bs[lrow][lcb + 4 * u + 2] = h23;
        }
        __syncthreads();

        #pragma unroll
        for (int ks = 0; ks < 32; ks += 16) {
            #pragma unroll
            for (int i = 0; i < 2; i++) {
                int r0 = wm + i * 16 + gid;
                unsigned a0 = *(const unsigned*)&As[r0][ks + 2 * tig];
                unsigned a1 = *(const unsigned*)&As[r0 + 8][ks + 2 * tig];
                unsigned a2 = *(const unsigned*)&As[r0][ks + 2 * tig + 8];
                unsigned a3 = *(const unsigned*)&As[r0 + 8][ks + 2 * tig + 8];
                #pragma unroll
                for (int j = 0; j < 8; j++) {
                    int n0 = wn + j * 8 + gid;
                    unsigned b0 = *(const unsigned*)&Bs[n0][ks + 2 * tig];
                    unsigned b1 = *(const unsigned*)&Bs[n0][ks + 2 * tig + 8];
                    mma_f16(c[i][j], a0, a1, a2, a3, b0, b1);
                }
            }
        }
        __syncthreads();
    }

    #pragma unroll
    for (int i = 0; i < 2; i++) {
        int r0 = bm + wm + i * 16 + gid;
        int r1 = r0 + 8;
        #pragma unroll
        for (int j = 0; j < 8; j++) {
            int col = bn + wn + j * 8 + 2 * tig;
            if (r0 < rows) *(float2*)&C[(size_t)(row0 + r0) * DD + col] = make_float2(c[i][j].x, c[i][j].y);
            if (r1 < rows) *(float2*)&C[(size_t)(row0 + r1) * DD + col] = make_float2(c[i][j].z, c[i][j].w);
        }
    }
}

// ---------------- fused edge MLP, layer-1 straight into MMA fragments ----------------
__global__ void __launch_bounds__(256)
k_edge_mlp_tc(const float* __restrict__ ea_g,
              const float* __restrict__ w1, const float* __restrict__ b1,
              const float* __restrict__ w2, const float* __restrict__ b2) {
    __shared__ float ea_s[128][8];
    __shared__ float w1p[256 * 8];
    __shared__ float w2sm[16][260];
    __shared__ float b2s[16];

    int tid = threadIdx.x;
    int ebase = blockIdx.x * 128;

    for (int idx = tid; idx < 128 * 6; idx += 256)
        ea_s[idx / 6][idx % 6] = ea_g[(size_t)ebase * 6 + idx];
    for (int idx = tid; idx < 256 * 8; idx += 256) {
        int j = idx >> 3, cc = idx & 7;
        float v = 0.0f;
        if (cc < 6)       v = w1[j * 6 + cc];
        else if (cc == 6) v = b1[j];
        w1p[idx] = v;
    }
    for (int idx = tid; idx < 16 * 256; idx += 256)
        w2sm[idx >> 8][idx & 255] = w2[idx];
    if (tid < 16) b2s[tid] = b2[tid];
    __syncthreads();

    int w = tid >> 5;
    int lane = tid & 31;
    int gid = lane >> 2;
    int tig = lane & 3;
    int e0 = 16 * w + gid;
    int e1 = e0 + 8;

    float eaA[6], eaB[6];
    #pragma unroll
    for (int k = 0; k < 6; k++) { eaA[k] = ea_s[e0][k]; eaB[k] = ea_s[e1][k]; }

    const float4* w1p4 = (const float4*)w1p;

    float4 c[2];
    c[0] = make_float4(0.f, 0.f, 0.f, 0.f);
    c[1] = make_float4(0.f, 0.f, 0.f, 0.f);

    #pragma unroll 4
    for (int k0 = 0; k0 < 256; k0 += 8) {
        int j0 = k0 + tig;
        int j1 = j0 + 4;
        float4 p0a = w1p4[j0 * 2 + 0], p0b = w1p4[j0 * 2 + 1];
        float4 p1a = w1p4[j1 * 2 + 0], p1b = w1p4[j1 * 2 + 1];

        float s0 = p0b.z, s1 = p0b.z, s2 = p1b.z, s3 = p1b.z;
        s0 = fmaf(eaA[0], p0a.x, s0); s0 = fmaf(eaA[1], p0a.y, s0);
        s0 = fmaf(eaA[2], p0a.z, s0); s0 = fmaf(eaA[3], p0a.w, s0);
        s0 = fmaf(eaA[4], p0b.x, s0); s0 = fmaf(eaA[5], p0b.y, s0);
        s1 = fmaf(eaB[0], p0a.x, s1); s1 = fmaf(eaB[1], p0a.y, s1);
        s1 = fmaf(eaB[2], p0a.z, s1); s1 = fmaf(eaB[3], p0a.w, s1);
        s1 = fmaf(eaB[4], p0b.x, s1); s1 = fmaf(eaB[5], p0b.y, s1);
        s2 = fmaf(eaA[0], p1a.x, s2); s2 = fmaf(eaA[1], p1a.y, s2);
        s2 = fmaf(eaA[2], p1a.z, s2); s2 = fmaf(eaA[3], p1a.w, s2);
        s2 = fmaf(eaA[4], p1b.x, s2); s2 = fmaf(eaA[5], p1b.y, s2);
        s3 = fmaf(eaB[0], p1a.x, s3); s3 = fmaf(eaB[1], p1a.y, s3);
        s3 = fmaf(eaB[2], p1a.z, s3); s3 = fmaf(eaB[3], p1a.w, s3);
        s3 = fmaf(eaB[4], p1b.x, s3); s3 = fmaf(eaB[5], p1b.y, s3);

        float a0 = gelu_f(s0);
        float a1 = gelu_f(s1);
        float a2 = gelu_f(s2);
        float a3 = gelu_f(s3);

        unsigned ah0 = f2tf32(a0), ah1 = f2tf32(a1), ah2 = f2tf32(a2), ah3 = f2tf32(a3);
        unsigned al0 = __float_as_uint(a0 - __uint_as_float(ah0));
        unsigned al1 = __float_as_uint(a1 - __uint_as_float(ah1));
        unsigned al2 = __float_as_uint(a2 - __uint_as_float(ah2));
        unsigned al3 = __float_as_uint(a3 - __uint_as_float(ah3));

        #pragma unroll
        for (int jn = 0; jn < 2; jn++) {
            float b0 = w2sm[jn * 8 + gid][j0];
            float b1v = w2sm[jn * 8 + gid][j1];
            unsigned bh0 = f2tf32(b0), bh1 = f2tf32(b1v);
            unsigned bl0 = __float_as_uint(b0 - __uint_as_float(bh0));
            unsigned bl1 = __float_as_uint(b1v - __uint_as_float(bh1));
            mma_tf32(c[jn], ah0, ah1, ah2, ah3, bh0, bh1);
            mma_tf32(c[jn], ah0, ah1, ah2, ah3, bl0, bl1);
            mma_tf32(c[jn], al0, al1, al2, al3, bh0, bh1);
        }
    }

    size_t ge0 = (size_t)(ebase + e0) * 16;
    size_t ge1 = (size_t)(ebase + e1) * 16;
    #pragma unroll
    for (int jn = 0; jn < 2; jn++) {
        int col = jn * 8 + 2 * tig;
        float bb0 = b2s[col], bb1 = b2s[col + 1];
        *(float2*)&g_exp[ge0 + col] = make_float2(__expf(c[jn].x + bb0), __expf(c[jn].y + bb1));
        *(float2*)&g_exp[ge1 + col] = make_float2(__expf(c[jn].z + bb0), __expf(c[jn].w + bb1));
    }
}

// ---------------- per-node aggregation: SINGLE pass via linearity ----------------
// out_n = (sum_i e1_i V_i)/s1 - beta*(sum_i e2_i V_i)/s2.  One sweep accumulates
// acc1, acc2, s1, s2; exp and V each read once per edge. attn_out written by a
// light 4-edges-per-iteration loop afterwards.
__device__ __forceinline__ void agg_one(int idx, int lane, int h,
                                        float& s1, float& s2, float* a1, float* a2) {
    int eid = g_eid[idx];
    int src = g_esrc[idx];
    float2 ee = *(const float2*)&g_exp[(size_t)eid * 16 + 2 * h];
    s1 += ee.x;
    s2 += ee.y;
    uint4 pv = *(const uint4*)&g_Vh[(size_t)src * DD + lane * 8];
    __half2 h0 = *(__half2*)&pv.x;
    __half2 h1 = *(__half2*)&pv.y;
    __half2 h2 = *(__half2*)&pv.z;
    __half2 h3 = *(__half2*)&pv.w;
    float2 f0 = __half22float2(h0), f1 = __half22float2(h1);
    float2 f2 = __half22float2(h2), f3 = __half22float2(h3);
    a1[0] = fmaf(ee.x, f0.x, a1[0]); a2[0] = fmaf(ee.y, f0.x, a2[0]);
    a1[1] = fmaf(ee.x, f0.y, a1[1]); a2[1] = fmaf(ee.y, f0.y, a2[1]);
    a1[2] = fmaf(ee.x, f1.x, a1[2]); a2[2] = fmaf(ee.y, f1.x, a2[2]);
    a1[3] = fmaf(ee.x, f1.y, a1[3]); a2[3] = fmaf(ee.y, f1.y, a2[3]);
    a1[4] = fmaf(ee.x, f2.x, a1[4]); a2[4] = fmaf(ee.y, f2.x, a2[4]);
    a1[5] = fmaf(ee.x, f2.y, a1[5]); a2[5] = fmaf(ee.y, f2.y, a2[5]);
    a1[6] = fmaf(ee.x, f3.x, a1[6]); a2[6] = fmaf(ee.y, f3.x, a2[6]);
    a1[7] = fmaf(ee.x, f3.y, a1[7]); a2[7] = fmaf(ee.y, f3.y, a2[7]);
}

__global__ void k_agg(float* __restrict__ attn_out, int n0, int n1) {
    int n = n0 + ((blockIdx.x * blockDim.x + threadIdx.x) >> 5);
    if (n >= n1) return;
    int lane = threadIdx.x & 31;
    int h = lane >> 2;

    int start = g_off[n];
    int cnt = g_cnt[n];
    float beta = g_beta;

    float s1 = 0.f, s2 = 0.f;
    float a1[8] = {0.f, 0.f, 0.f, 0.f, 0.f, 0.f, 0.f, 0.f};
    float a2[8] = {0.f, 0.f, 0.f, 0.f, 0.f, 0.f, 0.f, 0.f};

    int i = 0;
    for (; i + 1 < cnt; i += 2) {
        agg_one(start + i,     lane, h, s1, s2, a1, a2);
        agg_one(start + i + 1, lane, h, s1, s2, a1, a2);
    }
    if (i < cnt) agg_one(start + i, lane, h, s1, s2, a1, a2);

    float inv1 = (cnt > 0) ? 1.0f / s1 : 0.0f;
    float inv2 = (cnt > 0) ? beta / s2 : 0.0f;

    float o[8];
    #pragma unroll
    for (int k = 0; k < 8; k++)
        o[k] = a1[k] * inv1 - a2[k] * inv2;

    __half2 h0 = __floats2half2_rn(o[0], o[1]);
    __half2 h1 = __floats2half2_rn(o[2], o[3]);
    __half2 h2 = __floats2half2_rn(o[4], o[5]);
    __half2 h3 = __floats2half2_rn(o[6], o[7]);
    uint4 pack;
    pack.x = *(unsigned*)&h0;
    pack.y = *(unsigned*)&h1;
    pack.z = *(unsigned*)&h2;
    pack.w = *(unsigned*)&h3;
    *(uint4*)&g_acch[(size_t)n * DD + lane * 8] = pack;

    // light attn_out loop: lane (h, lane&3) covers edges i == (lane&3) mod 4
    if (attn_out) {
        float i1 = (cnt > 0) ? 1.0f / s1 : 0.0f;
        float i2 = (cnt > 0) ? beta / s2 : 0.0f;
        for (int j = lane & 3; j < cnt; j += 4) {
            int eid = g_eid[start + j];
            float2 ee = *(const float2*)&g_exp[(size_t)eid * 16 + 2 * h];
            attn_out[(size_t)eid * HH + h] = ee.x * i1 - ee.y * i2;
        }
    }
}

// ---------------- launch (stream-overlapped, graph-capturable fork/join) ----------------
extern "C" void kernel_launch(void* const* d_in, const int* in_sizes, int n_in,
                              void* d_out, int out_size) {
    const float* x    = (const float*)d_in[0];
    const float* eatt = (const float*)d_in[1];
    const float* v_w  = (const float*)d_in[2];
    const float* o_w  = (const float*)d_in[3];
    const float* e_w1 = (const float*)d_in[4];
    const float* e_b1 = (const float*)d_in[5];
    const float* e_w2 = (const float*)d_in[6];
    const float* e_b2 = (const float*)d_in[7];
    const float* lq   = (const float*)d_in[8];
    const float* lk   = (const float*)d_in[9];
    const void*  ei   = d_in[10];

    float* out = (float*)d_out;
    float* attn_out = (out_size >= ND + EH)     ? out + ND      : nullptr;
    float* beta_out = (out_size >= ND + EH + 1) ? out + ND + EH : nullptr;

    __half* gVh;
    __half* gAcch;
    cudaGetSymbolAddress((void**)&gVh, g_Vh);
    cudaGetSymbolAddress((void**)&gAcch, g_acch);

    static cudaStream_t sA = nullptr, sB = nullptr;
    static cudaEvent_t evRoot = nullptr, evA = nullptr, evB = nullptr,
                       evC = nullptr, evD = nullptr;
    if (!sA) {
        cudaStreamCreateWithFlags(&sA, cudaStreamNonBlocking);
        cudaStreamCreateWithFlags(&sB, cudaStreamNonBlocking);
        cudaEventCreateWithFlags(&evRoot, cudaEventDisableTiming);
        cudaEventCreateWithFlags(&evA, cudaEventDisableTiming);
        cudaEventCreateWithFlags(&evB, cudaEventDisableTiming);
        cudaEventCreateWithFlags(&evC, cudaEventDisableTiming);
        cudaEventCreateWithFlags(&evD, cudaEventDisableTiming);
    }

    dim3 ggrid(DD / 128, (NN + 127) / 128);

    // fork point on the capture (default) stream
    cudaEventRecord(evRoot, 0);

    // stream A: GEMM1 (independent of build/MLP)
    cudaStreamWaitEvent(sA, evRoot, 0);
    k_gemm_tc<<<ggrid, 256, 0, sA>>>(x, v_w, gVh, NN);
    cudaEventRecord(evA, sA);

    // stream B: edge MLP (independent of build/GEMM1)
    cudaStreamWaitEvent(sB, evRoot, 0);
    k_edge_mlp_tc<<<EE / 128, 256, 0, sB>>>(eatt, e_w1, e_b1, e_w2, e_b2);
    cudaEventRecord(evB, sB);

    // main stream: prologue + CSR build
    k_prolog<<<(NN + 255) / 256, 256>>>(ei, lq, lk, beta_out);
    k_hist<<<EE / 256, 256>>>(ei);
    k_scan<<<1, 1024>>>();
    k_fill<<<EE / 256, 256>>>(ei);

    // join
    cudaStreamWaitEvent(0, evA, 0);
    cudaStreamWaitEvent(0, evB, 0);

    // chunked agg / GEMM2 overlap:
    //   agg[0,NC0) -> (agg[NC0,NN) || gemm2 chunk0 on sA) -> gemm2 chunk1
    k_agg<<<(NC0 * 32 + 255) / 256, 256>>>(attn_out, 0, NC0);
    cudaEventRecord(evC, 0);
    k_agg<<<((NN - NC0) * 32 + 255) / 256, 256>>>(attn_out, NC0, NN);

    cudaStreamWaitEvent(sA, evC, 0);
    dim3 g2a(DD / 128, NC0 / 128);
    k_gemm2_h<<<g2a, 256, 0, sA>>>(gAcch, o_w, out, 0, NC0);
    cudaEventRecord(evD, sA);

    dim3 g2b(DD / 128, (NN - NC0 + 127) / 128);
    k_gemm2_h<<<g2b, 256>>>(gAcch, o_w, out, NC0, NN - NC0);
    cudaStreamWaitEvent(0, evD, 0);
}

// round 17
// speedup vs baseline: 1.1759x; 1.1759x over previous
#include <cuda_runtime.h>
#include <cuda_fp16.h>
#include <math.h>

#define NN 50000
#define EE 800000
#define DD 256
#define HH 8
#define ND (NN * DD)
#define EH (EE * HH)
#define LAMBDA_INIT 0.6321205588285577f

// ---------------- scratch (static device globals; no allocation) ----------------
__device__ __half g_Vh[ND];        // V = x @ v_w^T (fp16)   25.6 MB
__device__ float  g_exp[EE * 16];  // exp(scores), edge order 51.2 MB
__device__ __half g_acch[ND];      // aggregated output fp16 25.6 MB
__device__ int    g_cnt[NN];       // per-node degree
__device__ int    g_off[NN];       // CSR offsets
__device__ int    g_cur[NN];       // fill cursors
__device__ int    g_eid[EE];       // sorted edge ids
__device__ int    g_esrc[EE];      // sorted src nodes
__device__ float  g_beta;
__device__ int    g_is64;

// ---------------- helpers ----------------
__device__ __forceinline__ int ldidx(const void* p, long long i, int is64) {
    return is64 ? (int)((const long long*)p)[i] : ((const int*)p)[i];
}
__device__ __forceinline__ unsigned f2tf32(float x) {
    unsigned r;
    asm("cvt.rna.tf32.f32 %0, %1;" : "=r"(r) : "f"(x));
    return r;
}
__device__ __forceinline__ void mma_tf32(float4& c,
                                         unsigned a0, unsigned a1, unsigned a2, unsigned a3,
                                         unsigned b0, unsigned b1) {
    asm volatile("mma.sync.aligned.m16n8k8.row.col.f32.tf32.tf32.f32 "
                 "{%0,%1,%2,%3}, {%4,%5,%6,%7}, {%8,%9}, {%0,%1,%2,%3};"
                 : "+f"(c.x), "+f"(c.y), "+f"(c.z), "+f"(c.w)
                 : "r"(a0), "r"(a1), "r"(a2), "r"(a3), "r"(b0), "r"(b1));
}
__device__ __forceinline__ void mma_f16(float4& c,
                                        unsigned a0, unsigned a1, unsigned a2, unsigned a3,
                                        unsigned b0, unsigned b1) {
    asm volatile("mma.sync.aligned.m16n8k16.row.col.f32.f16.f16.f32 "
                 "{%0,%1,%2,%3}, {%4,%5,%6,%7}, {%8,%9}, {%0,%1,%2,%3};"
                 : "+f"(c.x), "+f"(c.y), "+f"(c.z), "+f"(c.w)
                 : "r"(a0), "r"(a1), "r"(a2), "r"(a3), "r"(b0), "r"(b1));
}

// exact-enough GELU: s * Phi(s), Phi via Abramowitz-Stegun 7.1.26 erf (abs err 1.5e-7)
__device__ __forceinline__ float gelu_f(float s) {
    float x  = s * 0.70710678118654752f;
    float ax = fabsf(x);
    float t  = __fdividef(1.0f, fmaf(0.3275911f, ax, 1.0f));
    float p  = fmaf(1.061405429f, t, -1.453152027f);
    p = fmaf(p, t, 1.421413741f);
    p = fmaf(p, t, -0.284496736f);
    p = fmaf(p, t, 0.254829592f);
    p *= t;
    float e = __expf(-x * x);
    float erfax = fmaf(-p, e, 1.0f);
    float erfx  = copysignf(erfax, x);
    return s * 0.5f * (1.0f + erfx);
}

// ---------------- fused prologue: zero counters + dtype sniff + beta ----------------
__global__ void k_prolog(const void* ei, const float* __restrict__ lq,
                         const float* __restrict__ lk, float* out_beta) {
    int i = blockIdx.x * blockDim.x + threadIdx.x;
    if (i < NN) g_cnt[i] = 0;

    if (blockIdx.x == 0) {
        int t = threadIdx.x;
        const int* p = (const int*)ei;
        int nz = (p[2 * t + 1] != 0);
        int any = __syncthreads_or(nz);
        if (t == 0) g_is64 = !any;
        __shared__ float red[128];
        if (t < 128) {
            float pr = (t < 100) ? lq[t] * lk[t] : 0.0f;
            red[t] = pr;
        }
        __syncthreads();
        for (int s = 64; s > 0; s >>= 1) {
            if (t < s) red[t] += red[t + s];
            __syncthreads();
        }
        if (t == 0) {
            float lam1 = expf(red[0]);
            float b = 1.0f / (1.0f + expf(-lam1 * LAMBDA_INIT));
            g_beta = b;
            if (out_beta) *out_beta = b;
        }
    }
}

// ---------------- CSR build ----------------
__global__ void k_hist(const void* __restrict__ ei) {
    int e = blockIdx.x * blockDim.x + threadIdx.x;
    if (e >= EE) return;
    int tgt = ldidx(ei, (long long)EE + e, g_is64);
    atomicAdd(&g_cnt[tgt], 1);
}

__global__ void k_scan() {
    __shared__ int s[1024];
    __shared__ int carry;
    int tid = threadIdx.x;
    if (tid == 0) carry = 0;
    __syncthreads();
    for (int base = 0; base < NN; base += 1024) {
        int i = base + tid;
        int v = (i < NN) ? g_cnt[i] : 0;
        s[tid] = v;
        __syncthreads();
        #pragma unroll
        for (int d = 1; d < 1024; d <<= 1) {
            int t = (tid >= d) ? s[tid - d] : 0;
            __syncthreads();
            s[tid] += t;
            __syncthreads();
        }
        int excl = s[tid] - v + carry;
        if (i < NN) { g_off[i] = excl; g_cur[i] = excl; }
        __syncthreads();
        if (tid == 0) carry += s[1023];
        __syncthreads();
    }
}

__global__ void k_fill(const void* __restrict__ ei) {
    int e = blockIdx.x * blockDim.x + threadIdx.x;
    if (e >= EE) return;
    int is64 = g_is64;
    int tgt = ldidx(ei, (long long)EE + e, is64);
    int src = ldidx(ei, e, is64);
    int pos = atomicAdd(&g_cur[tgt], 1);
    g_eid[pos] = e;
    g_esrc[pos] = src;
}

// ---------------- tensor-core GEMM1 (2xTF32): Vh[M,256] = A[M,256] @ B[256,256]^T -----
// a ≈ ahi (tf32), b = bhi + blo; C += ahi*bhi + ahi*blo.  Residual alo dropped:
// adds ~2.8e-4 rms error to V, absorbed by the existing fp16-V budget.
__global__ void __launch_bounds__(256, 2)
k_gemm_tc(const float* __restrict__ A, const float* __restrict__ B,
          __half* __restrict__ Ch, int M) {
    __shared__ float As[128][36];
    __shared__ float Bs[128][36];

    int bm = blockIdx.y * 128, bn = blockIdx.x * 128;
    int tid = threadIdx.x;
    int w = tid >> 5;
    int lane = tid & 31;
    int gid = lane >> 2;
    int tig = lane & 3;
    int wm = (w & 3) * 32;
    int wn = (w >> 2) * 64;

    int lrow = tid >> 1;
    int lcb = (tid & 1) * 16;
    int arow = bm + lrow;
    bool inM = (arow < M);
    const float* Arow = &A[(size_t)(inM ? arow : 0) * DD];
    const float* Brow = &B[(size_t)(bn + lrow) * DD];

    float4 c[2][8];
    #pragma unroll
    for (int i = 0; i < 2; i++)
        #pragma unroll
        for (int j = 0; j < 8; j++)
            c[i][j] = make_float4(0.f, 0.f, 0.f, 0.f);

    #pragma unroll 1
    for (int k0 = 0; k0 < 256; k0 += 32) {
        #pragma unroll
        for (int u = 0; u < 4; u++) {
            float4 av = inM ? *(const float4*)&Arow[k0 + lcb + 4 * u]
                            : make_float4(0.f, 0.f, 0.f, 0.f);
            float4 bv = *(const float4*)&Brow[k0 + lcb + 4 * u];
            *(float4*)&As[lrow][lcb + 4 * u] = av;
            *(float4*)&Bs[lrow][lcb + 4 * u] = bv;
        }
        __syncthreads();

        #pragma unroll
        for (int kk = 0; kk < 32; kk += 8) {
            unsigned ahi[2][4];
            #pragma unroll
            for (int i = 0; i < 2; i++) {
                int r0 = wm + i * 16 + gid;
                ahi[i][0] = f2tf32(As[r0][kk + tig]);
                ahi[i][1] = f2tf32(As[r0 + 8][kk + tig]);
                ahi[i][2] = f2tf32(As[r0][kk + tig + 4]);
                ahi[i][3] = f2tf32(As[r0 + 8][kk + tig + 4]);
            }
            #pragma unroll
            for (int j = 0; j < 8; j++) {
                int n0 = wn + j * 8 + gid;
                float b0 = Bs[n0][kk + tig];
                float b1 = Bs[n0][kk + tig + 4];
                unsigned bh0 = f2tf32(b0), bh1 = f2tf32(b1);
                unsigned bl0 = __float_as_uint(b0 - __uint_as_float(bh0));
                unsigned bl1 = __float_as_uint(b1 - __uint_as_float(bh1));
                #pragma unroll
                for (int i = 0; i < 2; i++) {
                    mma_tf32(c[i][j], ahi[i][0], ahi[i][1], ahi[i][2], ahi[i][3], bh0, bh1);
                    mma_tf32(c[i][j], ahi[i][0], ahi[i][1], ahi[i][2], ahi[i][3], bl0, bl1);
                }
            }
        }
        __syncthreads();
    }

    #pragma unroll
    for (int i = 0; i < 2; i++) {
        int r0 = bm + wm + i * 16 + gid;
        int r1 = r0 + 8;
        #pragma unroll
        for (int j = 0; j < 8; j++) {
            int col = bn + wn + j * 8 + 2 * tig;
            if (r0 < M) {
                __half2 h = __floats2half2_rn(c[i][j].x, c[i][j].y);
                *(__half2*)&Ch[(size_t)r0 * DD + col] = h;
            }
            if (r1 < M) {
                __half2 h = __floats2half2_rn(c[i][j].z, c[i][j].w);
                *(__half2*)&Ch[(size_t)r1 * DD + col] = h;
            }
        }
    }
}

// ---------------- GEMM2 (fp16 HMMA): C[M,256] = Ah[M,256] @ B[256,256]^T --------------
__global__ void __launch_bounds__(256, 2)
k_gemm2_h(const __half* __restrict__ A, const float* __restrict__ B,
          float* __restrict__ C, int M) {
    __shared__ __half As[128][40];
    __shared__ __half Bs[128][40];

    int bm = blockIdx.y * 128, bn = blockIdx.x * 128;
    int tid = threadIdx.x;
    int w = tid >> 5;
    int lane = tid & 31;
    int gid = lane >> 2;
    int tig = lane & 3;
    int wm = (w & 3) * 32;
    int wn = (w >> 2) * 64;

    int lrow = tid >> 1;
    int lcb = (tid & 1) * 16;
    int arow = bm + lrow;
    bool inM = (arow < M);
    const __half* Arow = &A[(size_t)(inM ? arow : 0) * DD];
    const float* Brow = &B[(size_t)(bn + lrow) * DD];

    float4 c[2][8];
    #pragma unroll
    for (int i = 0; i < 2; i++)
        #pragma unroll
        for (int j = 0; j < 8; j++)
            c[i][j] = make_float4(0.f, 0.f, 0.f, 0.f);

    #pragma unroll 1
    for (int k0 = 0; k0 < 256; k0 += 32) {
        uint4 zz = make_uint4(0u, 0u, 0u, 0u);
        uint4 av0 = inM ? *(const uint4*)&Arow[k0 + lcb]     : zz;
        uint4 av1 = inM ? *(const uint4*)&Arow[k0 + lcb + 8] : zz;
        *(uint4*)&As[lrow][lcb]     = av0;
        *(uint4*)&As[lrow][lcb + 8] = av1;
        #pragma unroll
        for (int u = 0; u < 4; u++) {
            float4 bv = *(const float4*)&Brow[k0 + lcb + 4 * u];
            __half2 h01 = __floats2half2_rn(bv.x, bv.y);
            __half2 h23 = __floats2half2_rn(bv.z, bv.w);
            *(__half2*)&Bs[lrow][lcb + 4 * u]     = h01;
            *(__half2*)&Bs[lrow][lcb + 4 * u + 2] = h23;
        }
        __syncthreads();

        #pragma unroll
        for (int ks = 0; ks < 32; ks += 16) {
            #pragma unroll
            for (int i = 0; i < 2; i++) {
                int r0 = wm + i * 16 + gid;
                unsigned a0 = *(const unsigned*)&As[r0][ks + 2 * tig];
                unsigned a1 = *(const unsigned*)&As[r0 + 8][ks + 2 * tig];
                unsigned a2 = *(const unsigned*)&As[r0][ks + 2 * tig + 8];
                unsigned a3 = *(const unsigned*)&As[r0 + 8][ks + 2 * tig + 8];
                #pragma unroll
                for (int j = 0; j < 8; j++) {
                    int n0 = wn + j * 8 + gid;
                    unsigned b0 = *(const unsigned*)&Bs[n0][ks + 2 * tig];
                    unsigned b1 = *(const unsigned*)&Bs[n0][ks + 2 * tig + 8];
                    mma_f16(c[i][j], a0, a1, a2, a3, b0, b1);
                }
            }
        }
        __syncthreads();
    }

    #pragma unroll
    for (int i = 0; i < 2; i++) {
        int r0 = bm + wm + i * 16 + gid;
        int r1 = r0 + 8;
        #pragma unroll
        for (int j = 0; j < 8; j++) {
            int col = bn + wn + j * 8 + 2 * tig;
            if (r0 < M) *(float2*)&C[(size_t)r0 * DD + col] = make_float2(c[i][j].x, c[i][j].y);
            if (r1 < M) *(float2*)&C[(size_t)r1 * DD + col] = make_float2(c[i][j].z, c[i][j].w);
        }
    }
}

// ---------------- fused edge MLP, layer-1 into fragments; layer-2 = 1xTF32 -----------
__global__ void __launch_bounds__(256)
k_edge_mlp_tc(const float* __restrict__ ea_g,
              const float* __restrict__ w1, const float* __restrict__ b1,
              const float* __restrict__ w2, const float* __restrict__ b2) {
    __shared__ float ea_s[128][8];
    __shared__ float w1p[256 * 8];
    __shared__ float w2sm[16][260];
    __shared__ float b2s[16];

    int tid = threadIdx.x;
    int ebase = blockIdx.x * 128;

    for (int idx = tid; idx < 128 * 6; idx += 256)
        ea_s[idx / 6][idx % 6] = ea_g[(size_t)ebase * 6 + idx];
    for (int idx = tid; idx < 256 * 8; idx += 256) {
        int j = idx >> 3, cc = idx & 7;
        float v = 0.0f;
        if (cc < 6)       v = w1[j * 6 + cc];
        else if (cc == 6) v = b1[j];
        w1p[idx] = v;
    }
    for (int idx = tid; idx < 16 * 256; idx += 256)
        w2sm[idx >> 8][idx & 255] = w2[idx];
    if (tid < 16) b2s[tid] = b2[tid];
    __syncthreads();

    int w = tid >> 5;
    int lane = tid & 31;
    int gid = lane >> 2;
    int tig = lane & 3;
    int e0 = 16 * w + gid;
    int e1 = e0 + 8;

    float eaA[6], eaB[6];
    #pragma unroll
    for (int k = 0; k < 6; k++) { eaA[k] = ea_s[e0][k]; eaB[k] = ea_s[e1][k]; }

    const float4* w1p4 = (const float4*)w1p;

    float4 c[2];
    c[0] = make_float4(0.f, 0.f, 0.f, 0.f);
    c[1] = make_float4(0.f, 0.f, 0.f, 0.f);

    #pragma unroll 4
    for (int k0 = 0; k0 < 256; k0 += 8) {
        int j0 = k0 + tig;
        int j1 = j0 + 4;
        float4 p0a = w1p4[j0 * 2 + 0], p0b = w1p4[j0 * 2 + 1];
        float4 p1a = w1p4[j1 * 2 + 0], p1b = w1p4[j1 * 2 + 1];

        float s0 = p0b.z, s1 = p0b.z, s2 = p1b.z, s3 = p1b.z;
        s0 = fmaf(eaA[0], p0a.x, s0); s0 = fmaf(eaA[1], p0a.y, s0);
        s0 = fmaf(eaA[2], p0a.z, s0); s0 = fmaf(eaA[3], p0a.w, s0);
        s0 = fmaf(eaA[4], p0b.x, s0); s0 = fmaf(eaA[5], p0b.y, s0);
        s1 = fmaf(eaB[0], p0a.x, s1); s1 = fmaf(eaB[1], p0a.y, s1);
        s1 = fmaf(eaB[2], p0a.z, s1); s1 = fmaf(eaB[3], p0a.w, s1);
        s1 = fmaf(eaB[4], p0b.x, s1); s1 = fmaf(eaB[5], p0b.y, s1);
        s2 = fmaf(eaA[0], p1a.x, s2); s2 = fmaf(eaA[1], p1a.y, s2);
        s2 = fmaf(eaA[2], p1a.z, s2); s2 = fmaf(eaA[3], p1a.w, s2);
        s2 = fmaf(eaA[4], p1b.x, s2); s2 = fmaf(eaA[5], p1b.y, s2);
        s3 = fmaf(eaB[0], p1a.x, s3); s3 = fmaf(eaB[1], p1a.y, s3);
        s3 = fmaf(eaB[2], p1a.z, s3); s3 = fmaf(eaB[3], p1a.w, s3);
        s3 = fmaf(eaB[4], p1b.x, s3); s3 = fmaf(eaB[5], p1b.y, s3);

        unsigned ah0 = f2tf32(gelu_f(s0));
        unsigned ah1 = f2tf32(gelu_f(s1));
        unsigned ah2 = f2tf32(gelu_f(s2));
        unsigned ah3 = f2tf32(gelu_f(s3));

        #pragma unroll
        for (int jn = 0; jn < 2; jn++) {
            unsigned bh0 = f2tf32(w2sm[jn * 8 + gid][j0]);
            unsigned bh1 = f2tf32(w2sm[jn * 8 + gid][j1]);
            mma_tf32(c[jn], ah0, ah1, ah2, ah3, bh0, bh1);
        }
    }

    size_t ge0 = (size_t)(ebase + e0) * 16;
    size_t ge1 = (size_t)(ebase + e1) * 16;
    #pragma unroll
    for (int jn = 0; jn < 2; jn++) {
        int col = jn * 8 + 2 * tig;
        float bb0 = b2s[col], bb1 = b2s[col + 1];
        *(float2*)&g_exp[ge0 + col] = make_float2(__expf(c[jn].x + bb0), __expf(c[jn].y + bb1));
        *(float2*)&g_exp[ge1 + col] = make_float2(__expf(c[jn].z + bb0), __expf(c[jn].w + bb1));
    }
}

// ---------------- per-node aggregation (two-pass, R14 winner) ----------------
__global__ void k_agg(float* __restrict__ attn_out) {
    int n = (blockIdx.x * blockDim.x + threadIdx.x) >> 5;
    if (n >= NN) return;
    int lane = threadIdx.x & 31;
    int h = lane >> 2;

    int start = g_off[n];
    int cnt = g_cnt[n];
    float beta = g_beta;

    // pass 1: lane covers component (lane&15); two edges in flight (lane>>4).
    int comp = lane & 15;
    float part = 0.f;
    for (int i = lane >> 4; i < cnt; i += 2) {
        int eid = g_eid[start + i];
        part += g_exp[(size_t)eid * 16 + comp];
    }
    part += __shfl_xor_sync(0xffffffffu, part, 16);
    float s1 = __shfl_sync(0xffffffffu, part, 2 * h);
    float s2 = __shfl_sync(0xffffffffu, part, 2 * h + 1);
    float inv1 = (cnt > 0) ? 1.0f / s1 : 0.0f;
    float inv2 = (cnt > 0) ? 1.0f / s2 : 0.0f;

    // pass 2: attn + gather + accumulate
    float acc[8] = {0.f, 0.f, 0.f, 0.f, 0.f, 0.f, 0.f, 0.f};
    for (int i = 0; i < cnt; i++) {
        int eid = g_eid[start + i];
        int src = g_esrc[start + i];
        float2 ee = *(const float2*)&g_exp[(size_t)eid * 16 + 2 * h];
        float attn = ee.x * inv1 - beta * (ee.y * inv2);
        if (attn_out && (lane & 3) == 0)
            attn_out[(size_t)eid * HH + h] = attn;
        uint4 pv = *(const uint4*)&g_Vh[(size_t)src * DD + lane * 8];
        __half2 h0 = *(__half2*)&pv.x;
        __half2 h1 = *(__half2*)&pv.y;
        __half2 h2 = *(__half2*)&pv.z;
        __half2 h3 = *(__half2*)&pv.w;
        float2 f0 = __half22float2(h0), f1 = __half22float2(h1);
        float2 f2 = __half22float2(h2), f3 = __half22float2(h3);
        acc[0] = fmaf(attn, f0.x, acc[0]); acc[1] = fmaf(attn, f0.y, acc[1]);
        acc[2] = fmaf(attn, f1.x, acc[2]); acc[3] = fmaf(attn, f1.y, acc[3]);
        acc[4] = fmaf(attn, f2.x, acc[4]); acc[5] = fmaf(attn, f2.y, acc[5]);
        acc[6] = fmaf(attn, f3.x, acc[6]); acc[7] = fmaf(attn, f3.y, acc[7]);
    }

    __half2 o0 = __floats2half2_rn(acc[0], acc[1]);
    __half2 o1 = __floats2half2_rn(acc[2], acc[3]);
    __half2 o2 = __floats2half2_rn(acc[4], acc[5]);
    __half2 o3 = __floats2half2_rn(acc[6], acc[7]);
    uint4 pack;
    pack.x = *(unsigned*)&o0;
    pack.y = *(unsigned*)&o1;
    pack.z = *(unsigned*)&o2;
    pack.w = *(unsigned*)&o3;
    *(uint4*)&g_acch[(size_t)n * DD + lane * 8] = pack;
}

// ---------------- launch (stream-overlapped, graph-capturable fork/join) ----------------
extern "C" void kernel_launch(void* const* d_in, const int* in_sizes, int n_in,
                              void* d_out, int out_size) {
    const float* x    = (const float*)d_in[0];
    const float* eatt = (const float*)d_in[1];
    const float* v_w  = (const float*)d_in[2];
    const float* o_w  = (const float*)d_in[3];
    const float* e_w1 = (const float*)d_in[4];
    const float* e_b1 = (const float*)d_in[5];
    const float* e_w2 = (const float*)d_in[6];
    const float* e_b2 = (const float*)d_in[7];
    const float* lq   = (const float*)d_in[8];
    const float* lk   = (const float*)d_in[9];
    const void*  ei   = d_in[10];

    float* out = (float*)d_out;
    float* attn_out = (out_size >= ND + EH)     ? out + ND      : nullptr;
    float* beta_out = (out_size >= ND + EH + 1) ? out + ND + EH : nullptr;

    __half* gVh;
    __half* gAcch;
    cudaGetSymbolAddress((void**)&gVh, g_Vh);
    cudaGetSymbolAddress((void**)&gAcch, g_acch);

    static cudaStream_t sA = nullptr, sB = nullptr;
    static cudaEvent_t evRoot = nullptr, evA = nullptr, evB = nullptr;
    if (!sA) {
        cudaStreamCreateWithFlags(&sA, cudaStreamNonBlocking);
        cudaStreamCreateWithFlags(&sB, cudaStreamNonBlocking);
        cudaEventCreateWithFlags(&evRoot, cudaEventDisableTiming);
        cudaEventCreateWithFlags(&evA, cudaEventDisableTiming);
        cudaEventCreateWithFlags(&evB, cudaEventDisableTiming);
    }

    dim3 ggrid(DD / 128, (NN + 127) / 128);

    // fork point on the capture (default) stream
    cudaEventRecord(evRoot, 0);

    // stream A: GEMM1 (independent of build/MLP)
    cudaStreamWaitEvent(sA, evRoot, 0);
    k_gemm_tc<<<ggrid, 256, 0, sA>>>(x, v_w, gVh, NN);
    cudaEventRecord(evA, sA);

    // stream B: edge MLP (independent of build/GEMM1)
    cudaStreamWaitEvent(sB, evRoot, 0);
    k_edge_mlp_tc<<<EE / 128, 256, 0, sB>>>(eatt, e_w1, e_b1, e_w2, e_b2);
    cudaEventRecord(evB, sB);

    // main stream: prologue + CSR build
    k_prolog<<<(NN + 255) / 256, 256>>>(ei, lq, lk, beta_out);
    k_hist<<<EE / 256, 256>>>(ei);
    k_scan<<<1, 1024>>>();
    k_fill<<<EE / 256, 256>>>(ei);

    // join
    cudaStreamWaitEvent(0, evA, 0);
    cudaStreamWaitEvent(0, evB, 0);

    k_agg<<<(NN * 32 + 255) / 256, 256>>>(attn_out);
    k_gemm2_h<<<ggrid, 256>>>(gAcch, o_w, out, NN);
}